// round 11
// baseline (speedup 1.0000x reference)
#include <cuda_runtime.h>
#include <cuda_fp16.h>
#include <math.h>

#define B_ROWS 4096
#define T_LEN  8192
#define SCAN_THREADS 512
#define NWARPS (SCAN_THREADS / 32)     // 16
#define CHUNK (T_LEN / SCAN_THREADS)   // 16
#define GROUPS (T_LEN / 4)             // 2048 float4-groups per row
#define GAMMA 0.99f
#define GAMMA16 0.8514577710948755f    // 0.99^16
#define EPS_N 1e-9f
#define RPAD 513                       // padded row stride (words) for transpose smem

// Scratch (device globals; no allocations allowed).
__device__ float    g_row_sum[B_ROWS];
__device__ float    g_row_inv[B_ROWS];
__device__ float    g_mean_val;
__device__ unsigned g_count;           // zero-init; atomicInc wraps -> self-reset per launch
// fp16 staging for unnormalized returns: 64 MB, L2-resident in steady state.
__device__ __align__(128) __half g_ret_h[(size_t)B_ROWS * T_LEN];

// ───────────────────────── scan: one block per row ─────────────────────────
// x_t = r_t + a_t * x_{t+1},  a_t = GAMMA*(1-done_t),  done in {0,1} exactly.
// All GMEM traffic coalesced; ownership transpose in smem (R10-proven).
__global__ __launch_bounds__(SCAN_THREADS, 3)
void scan_kernel(const float* __restrict__ rewards,
                 const float* __restrict__ dones)
{
    const int row  = blockIdx.x;
    const int tid  = threadIdx.x;
    const int lane = tid & 31;
    const int wid  = tid >> 5;
    const size_t row_off = (size_t)row * T_LEN;

    __shared__ float    s_rew[16 * RPAD];   // transposed rewards (and later results)
    __shared__ unsigned s_db[GROUPS];       // 4 done-bytes packed per word
    __shared__ float    sWA[NWARPS], sWB[NWARPS], sCB[NWARPS];
    __shared__ float    sS[NWARPS],  sQ[NWARPS];
    __shared__ unsigned s_last;

    // ── Phase 1: coalesced load (lane-contiguous float4 groups) -> smem ──
    const float4* r4 = reinterpret_cast<const float4*>(rewards + row_off);
    const float4* d4 = reinterpret_cast<const float4*>(dones   + row_off);
#pragma unroll
    for (int k = 0; k < 4; k++) {
        const int g = tid + 512 * k;
        float4 rv = __ldcs(r4 + g);
        float4 dv = __ldcs(d4 + g);
        const int c = (g & 3) * 4;
        const int q = g >> 2;
        s_rew[(c + 0) * RPAD + q] = rv.x;
        s_rew[(c + 1) * RPAD + q] = rv.y;
        s_rew[(c + 2) * RPAD + q] = rv.z;
        s_rew[(c + 3) * RPAD + q] = rv.w;
        unsigned p = (dv.x != 0.0f ? 1u : 0u)
                   | (dv.y != 0.0f ? 1u : 0u) << 8
                   | (dv.z != 0.0f ? 1u : 0u) << 16
                   | (dv.w != 0.0f ? 1u : 0u) << 24;
        s_db[g] = p;
    }
    __syncthreads();

    // ── Phase 2: owner gathers its 16 time-contiguous elements ──
    float r[CHUNK];
#pragma unroll
    for (int t = 0; t < CHUNK; t++)
        r[t] = s_rew[t * RPAD + tid];

    unsigned mask = 0;
    {
        const uint4 dw = *reinterpret_cast<const uint4*>(&s_db[tid * 4]);
        const unsigned w[4] = {dw.x, dw.y, dw.z, dw.w};
#pragma unroll
        for (int q = 0; q < 4; q++) {
            mask |= ((w[q] >> 0)  & 1u) << (4*q + 0);
            mask |= ((w[q] >> 8)  & 1u) << (4*q + 1);
            mask |= ((w[q] >> 16) & 1u) << (4*q + 2);
            mask |= ((w[q] >> 24) & 1u) << (4*q + 3);
        }
    }

    // Compose chunk into affine map (A, B): x_left = B + A * x_right.
    float A  = (mask == 0u) ? GAMMA16 : 0.0f;
    float Bc = 0.0f;
#pragma unroll
    for (int t = CHUNK - 1; t >= 0; t--) {
        float f = fmaf(GAMMA, Bc, r[t]);
        Bc = (mask & (1u << t)) ? r[t] : f;
    }

    // Warp-level inclusive SUFFIX scan via shuffles.
#pragma unroll
    for (int d = 1; d < 32; d <<= 1) {
        float A2 = __shfl_down_sync(0xFFFFFFFFu, A, d);
        float B2 = __shfl_down_sync(0xFFFFFFFFu, Bc, d);
        if (lane + d < 32) {
            Bc = fmaf(A, B2, Bc);
            A  = A * A2;
        }
    }

    if (lane == 0) { sWA[wid] = A; sWB[wid] = Bc; }
    __syncthreads();

    if (wid == 0) {
        float wA = (lane < NWARPS) ? sWA[lane] : 1.0f;
        float wB = (lane < NWARPS) ? sWB[lane] : 0.0f;
#pragma unroll
        for (int d = 1; d < NWARPS; d <<= 1) {
            float A2 = __shfl_down_sync(0xFFFFFFFFu, wA, d);
            float B2 = __shfl_down_sync(0xFFFFFFFFu, wB, d);
            if (lane + d < NWARPS) {
                wB = fmaf(wA, B2, wB);
                wA = wA * A2;
            }
        }
        float eB = __shfl_down_sync(0xFFFFFFFFu, wB, 1);
        if (lane == NWARPS - 1) eB = 0.0f;
        if (lane < NWARPS) sCB[lane] = eB;
    }
    __syncthreads();

    float cB   = sCB[wid];
    float totB = fmaf(A, cB, Bc);
    float carry = __shfl_down_sync(0xFFFFFFFFu, totB, 1);
    if (lane == 31) carry = cB;        // tid==511 -> cB==0, correct

    // ── Phase 3: replay with true carry; moments + transposed writeback ──
    float sum = 0.0f, sq = 0.0f;
#pragma unroll
    for (int t = CHUNK - 1; t >= 0; t--) {
        float f = fmaf(GAMMA, carry, r[t]);
        carry = (mask & (1u << t)) ? r[t] : f;
        r[t] = carry;
        sum += carry;
        sq = fmaf(carry, carry, sq);
    }
#pragma unroll
    for (int t = 0; t < CHUNK; t++)
        s_rew[t * RPAD + tid] = r[t];

    // Block reduction of (sum, sq).
#pragma unroll
    for (int d = 16; d > 0; d >>= 1) {
        sum += __shfl_down_sync(0xFFFFFFFFu, sum, d);
        sq  += __shfl_down_sync(0xFFFFFFFFu, sq,  d);
    }
    if (lane == 0) { sS[wid] = sum; sQ[wid] = sq; }
    __syncthreads();
    if (tid < 32) {
        float ts = (lane < NWARPS) ? sS[lane] : 0.0f;
        float tq = (lane < NWARPS) ? sQ[lane] : 0.0f;
#pragma unroll
        for (int d = NWARPS / 2; d > 0; d >>= 1) {
            ts += __shfl_down_sync(0xFFFFFFFFu, ts, d);
            tq += __shfl_down_sync(0xFFFFFFFFu, tq, d);
        }
        if (lane == 0) {
            float mean = ts / (float)T_LEN;
            float var  = (tq - ts * mean) / (float)(T_LEN - 1);   // ddof=1
            g_row_sum[row] = ts;
            g_row_inv[row] = 1.0f / (sqrtf(fmaxf(var, 0.0f)) + EPS_N);
        }
    }

    // ── Phase 4: coalesced fp16 staging store (lane-contiguous 8B units) ──
    uint2* stg = reinterpret_cast<uint2*>(g_ret_h + row_off);
#pragma unroll
    for (int k = 0; k < 4; k++) {
        const int g = tid + 512 * k;
        const int c = (g & 3) * 4;
        const int q = g >> 2;
        float v0 = s_rew[(c + 0) * RPAD + q];
        float v1 = s_rew[(c + 1) * RPAD + q];
        float v2 = s_rew[(c + 2) * RPAD + q];
        float v3 = s_rew[(c + 3) * RPAD + q];
        __half2 h0 = __floats2half2_rn(v0, v1);
        __half2 h1 = __floats2half2_rn(v2, v3);
        uint2 u;
        u.x = *reinterpret_cast<unsigned*>(&h0);
        u.y = *reinterpret_cast<unsigned*>(&h1);
        stg[g] = u;
    }

    // PDL: this CTA's dependent-launch obligation is done (correctness is
    // carried by the secondary's full-grid dependency sync, not this trigger).
    cudaTriggerProgrammaticLaunchCompletion();

    // Last block to finish reduces the 4096 row sums -> global mean.
    if (tid == 0) {
        __threadfence();
        unsigned prev = atomicInc(&g_count, B_ROWS - 1);   // wraps to 0: self-reset
        s_last = (prev == B_ROWS - 1) ? 1u : 0u;
    }
    __syncthreads();
    if (s_last) {
        float s = 0.0f;
#pragma unroll
        for (int i = 0; i < B_ROWS / SCAN_THREADS; i++)
            s += __ldcg(&g_row_sum[tid + i * SCAN_THREADS]);
#pragma unroll
        for (int d = 16; d > 0; d >>= 1)
            s += __shfl_down_sync(0xFFFFFFFFu, s, d);
        if (lane == 0) sS[wid] = s;
        __syncthreads();
        if (tid < 32) {
            float t = (lane < NWARPS) ? sS[lane] : 0.0f;
#pragma unroll
            for (int d = 16; d > 0; d >>= 1)
                t += __shfl_down_sync(0xFFFFFFFFu, t, d);
            if (tid == 0)
                g_mean_val = t / ((float)B_ROWS * (float)T_LEN);
        }
    }
}

// ── normalize: fully coalesced (R10-proven). PDL secondary: sync on scan grid
// before touching any scan-produced state. ──
__global__ __launch_bounds__(512)
void norm_kernel(float* __restrict__ out)
{
    const int row = blockIdx.x;
    const int tid = threadIdx.x;

    // Wait for the entire scan grid (staging + row stats + global mean visible).
    cudaGridDependencySynchronize();

    const float inv = g_row_inv[row];
    const float neg = -g_mean_val * inv;
    const size_t unit0 = (size_t)row * GROUPS + tid;

    const uint2* src = reinterpret_cast<const uint2*>(g_ret_h);
    float4* o4 = reinterpret_cast<float4*>(out);

    uint2 p[4];
#pragma unroll
    for (int k = 0; k < 4; k++)
        p[k] = __ldlu(src + unit0 + 512 * k);     // front-batched, coalesced

#pragma unroll
    for (int k = 0; k < 4; k++) {
        __half2 h0 = *reinterpret_cast<__half2*>(&p[k].x);
        __half2 h1 = *reinterpret_cast<__half2*>(&p[k].y);
        float2 a = __half22float2(h0);
        float2 b = __half22float2(h1);
        float4 v;
        v.x = fmaf(a.x, inv, neg);
        v.y = fmaf(a.y, inv, neg);
        v.z = fmaf(b.x, inv, neg);
        v.w = fmaf(b.y, inv, neg);
        __stcs(o4 + unit0 + 512 * k, v);
    }
}

extern "C" void kernel_launch(void* const* d_in, const int* in_sizes, int n_in,
                              void* d_out, int out_size)
{
    const float* rewards = (const float*)d_in[0];
    const float* dones   = (const float*)d_in[1];
    float* out = (float*)d_out;

    scan_kernel<<<B_ROWS, SCAN_THREADS>>>(rewards, dones);

    // Norm as a programmatic dependent launch: overlaps with scan's tail drain.
    cudaLaunchConfig_t cfg = {};
    cfg.gridDim  = dim3(B_ROWS, 1, 1);
    cfg.blockDim = dim3(512, 1, 1);
    cudaLaunchAttribute attrs[1];
    attrs[0].id = cudaLaunchAttributeProgrammaticStreamSerialization;
    attrs[0].val.programmaticStreamSerializationAllowed = 1;
    cfg.attrs = attrs;
    cfg.numAttrs = 1;
    cudaLaunchKernelEx(&cfg, norm_kernel, out);
}

// round 12
// speedup vs baseline: 1.0290x; 1.0290x over previous
#include <cuda_runtime.h>
#include <cuda_fp16.h>
#include <math.h>

#define B_ROWS 4096
#define T_LEN  8192
#define SCAN_THREADS 512
#define NWARPS (SCAN_THREADS / 32)     // 16
#define CHUNK (T_LEN / SCAN_THREADS)   // 16
#define GROUPS (T_LEN / 4)             // 2048 float4-groups per row
#define GAMMA 0.99f
#define GAMMA16 0.8514577710948755f    // 0.99^16
#define EPS_N 1e-9f
#define RPAD 513                       // padded row stride (words) for transpose smem

// Scratch (device globals; no allocations allowed).
__device__ float    g_row_sum[B_ROWS];
__device__ float    g_row_inv[B_ROWS];
__device__ float    g_mean_val;
__device__ unsigned g_count;           // zero-init; atomicInc wraps -> self-reset per launch
// fp16 staging for unnormalized returns: 64 MB, L2-resident in steady state.
__device__ __align__(128) __half g_ret_h[(size_t)B_ROWS * T_LEN];

// ───────────────────────── scan: one block per row ─────────────────────────
// x_t = r_t + a_t * x_{t+1},  a_t = GAMMA*(1-done_t),  done in {0,1} exactly.
// Coalesced loads via smem transpose; staging stored DIRECTLY from registers
// (thread-contiguous 32B: warp covers a contiguous 1KB — no smem round-trip).
__global__ __launch_bounds__(SCAN_THREADS, 3)
void scan_kernel(const float* __restrict__ rewards,
                 const float* __restrict__ dones)
{
    const int row  = blockIdx.x;
    const int tid  = threadIdx.x;
    const int lane = tid & 31;
    const int wid  = tid >> 5;
    const size_t row_off = (size_t)row * T_LEN;

    __shared__ float    s_rew[16 * RPAD];   // transposed rewards
    __shared__ unsigned s_db[GROUPS];       // 4 done-bytes packed per word
    __shared__ float    sWA[NWARPS], sWB[NWARPS], sCB[NWARPS];
    __shared__ float    sS[NWARPS],  sQ[NWARPS];
    __shared__ unsigned s_last;

    // ── Phase 1: coalesced load (lane-contiguous float4 groups) -> smem ──
    const float4* r4 = reinterpret_cast<const float4*>(rewards + row_off);
    const float4* d4 = reinterpret_cast<const float4*>(dones   + row_off);
#pragma unroll
    for (int k = 0; k < 4; k++) {
        const int g = tid + 512 * k;
        float4 rv = __ldcs(r4 + g);
        float4 dv = __ldcs(d4 + g);
        const int c = (g & 3) * 4;
        const int q = g >> 2;
        s_rew[(c + 0) * RPAD + q] = rv.x;
        s_rew[(c + 1) * RPAD + q] = rv.y;
        s_rew[(c + 2) * RPAD + q] = rv.z;
        s_rew[(c + 3) * RPAD + q] = rv.w;
        unsigned p = (dv.x != 0.0f ? 1u : 0u)
                   | (dv.y != 0.0f ? 1u : 0u) << 8
                   | (dv.z != 0.0f ? 1u : 0u) << 16
                   | (dv.w != 0.0f ? 1u : 0u) << 24;
        s_db[g] = p;
    }
    __syncthreads();

    // ── Phase 2: owner gathers its 16 time-contiguous elements ──
    float r[CHUNK];
#pragma unroll
    for (int t = 0; t < CHUNK; t++)
        r[t] = s_rew[t * RPAD + tid];

    unsigned mask = 0;
    {
        const uint4 dw = *reinterpret_cast<const uint4*>(&s_db[tid * 4]);
        const unsigned w[4] = {dw.x, dw.y, dw.z, dw.w};
#pragma unroll
        for (int q = 0; q < 4; q++) {
            mask |= ((w[q] >> 0)  & 1u) << (4*q + 0);
            mask |= ((w[q] >> 8)  & 1u) << (4*q + 1);
            mask |= ((w[q] >> 16) & 1u) << (4*q + 2);
            mask |= ((w[q] >> 24) & 1u) << (4*q + 3);
        }
    }

    // Compose chunk into affine map (A, B): x_left = B + A * x_right.
    float A  = (mask == 0u) ? GAMMA16 : 0.0f;
    float Bc = 0.0f;
#pragma unroll
    for (int t = CHUNK - 1; t >= 0; t--) {
        float f = fmaf(GAMMA, Bc, r[t]);
        Bc = (mask & (1u << t)) ? r[t] : f;
    }

    // Warp-level inclusive SUFFIX scan via shuffles.
#pragma unroll
    for (int d = 1; d < 32; d <<= 1) {
        float A2 = __shfl_down_sync(0xFFFFFFFFu, A, d);
        float B2 = __shfl_down_sync(0xFFFFFFFFu, Bc, d);
        if (lane + d < 32) {
            Bc = fmaf(A, B2, Bc);
            A  = A * A2;
        }
    }

    if (lane == 0) { sWA[wid] = A; sWB[wid] = Bc; }
    __syncthreads();

    if (wid == 0) {
        float wA = (lane < NWARPS) ? sWA[lane] : 1.0f;
        float wB = (lane < NWARPS) ? sWB[lane] : 0.0f;
#pragma unroll
        for (int d = 1; d < NWARPS; d <<= 1) {
            float A2 = __shfl_down_sync(0xFFFFFFFFu, wA, d);
            float B2 = __shfl_down_sync(0xFFFFFFFFu, wB, d);
            if (lane + d < NWARPS) {
                wB = fmaf(wA, B2, wB);
                wA = wA * A2;
            }
        }
        float eB = __shfl_down_sync(0xFFFFFFFFu, wB, 1);
        if (lane == NWARPS - 1) eB = 0.0f;
        if (lane < NWARPS) sCB[lane] = eB;
    }
    __syncthreads();

    float cB   = sCB[wid];
    float totB = fmaf(A, cB, Bc);
    float carry = __shfl_down_sync(0xFFFFFFFFu, totB, 1);
    if (lane == 31) carry = cB;        // tid==511 -> cB==0, correct

    // ── Phase 3: replay with true carry; moments; DIRECT staging store ──
    float sum = 0.0f, sq = 0.0f;
#pragma unroll
    for (int t = CHUNK - 1; t >= 0; t--) {
        float f = fmaf(GAMMA, carry, r[t]);
        carry = (mask & (1u << t)) ? r[t] : f;
        r[t] = carry;
        sum += carry;
        sq = fmaf(carry, carry, sq);
    }

    // Staging: thread's 16 halves = 32B contiguous at tid*32; a warp's two
    // STG.128 both land in the same contiguous 1KB (8 lines) -> L2 combines.
    {
        __half2 h[CHUNK / 2];
#pragma unroll
        for (int i = 0; i < CHUNK / 2; i++)
            h[i] = __floats2half2_rn(r[2*i], r[2*i+1]);
        uint4* dst = reinterpret_cast<uint4*>(g_ret_h + row_off + tid * CHUNK);
        const uint4* srcv = reinterpret_cast<const uint4*>(h);
        dst[0] = srcv[0];
        dst[1] = srcv[1];
    }

    // Block reduction of (sum, sq).
#pragma unroll
    for (int d = 16; d > 0; d >>= 1) {
        sum += __shfl_down_sync(0xFFFFFFFFu, sum, d);
        sq  += __shfl_down_sync(0xFFFFFFFFu, sq,  d);
    }
    if (lane == 0) { sS[wid] = sum; sQ[wid] = sq; }
    __syncthreads();
    if (tid < 32) {
        float ts = (lane < NWARPS) ? sS[lane] : 0.0f;
        float tq = (lane < NWARPS) ? sQ[lane] : 0.0f;
#pragma unroll
        for (int d = NWARPS / 2; d > 0; d >>= 1) {
            ts += __shfl_down_sync(0xFFFFFFFFu, ts, d);
            tq += __shfl_down_sync(0xFFFFFFFFu, tq, d);
        }
        if (lane == 0) {
            float mean = ts / (float)T_LEN;
            float var  = (tq - ts * mean) / (float)(T_LEN - 1);   // ddof=1
            g_row_sum[row] = ts;
            g_row_inv[row] = 1.0f / (sqrtf(fmaxf(var, 0.0f)) + EPS_N);
        }
    }

    // Last block to finish reduces the 4096 row sums -> global mean.
    if (tid == 0) {
        __threadfence();
        unsigned prev = atomicInc(&g_count, B_ROWS - 1);   // wraps to 0: self-reset
        s_last = (prev == B_ROWS - 1) ? 1u : 0u;
    }
    __syncthreads();
    if (s_last) {
        float s = 0.0f;
#pragma unroll
        for (int i = 0; i < B_ROWS / SCAN_THREADS; i++)
            s += __ldcg(&g_row_sum[tid + i * SCAN_THREADS]);
#pragma unroll
        for (int d = 16; d > 0; d >>= 1)
            s += __shfl_down_sync(0xFFFFFFFFu, s, d);
        if (lane == 0) sS[wid] = s;
        __syncthreads();
        if (tid < 32) {
            float t = (lane < NWARPS) ? sS[lane] : 0.0f;
#pragma unroll
            for (int d = 16; d > 0; d >>= 1)
                t += __shfl_down_sync(0xFFFFFFFFu, t, d);
            if (tid == 0)
                g_mean_val = t / ((float)B_ROWS * (float)T_LEN);
        }
    }
}

// ── normalize: fully coalesced, MLP=8. One block per row; 256 threads,
// 8 unit-interleaved loads per thread (unit = 4 elements, stride 256). ──
#define NORM_TPB 256
#define NORM_UNITS 8
__global__ __launch_bounds__(NORM_TPB)
void norm_kernel(float* __restrict__ out)
{
    const int row = blockIdx.x;
    const float inv = g_row_inv[row];
    const float neg = -g_mean_val * inv;
    const size_t unit0 = (size_t)row * GROUPS + threadIdx.x;

    const uint2* src = reinterpret_cast<const uint2*>(g_ret_h);
    float4* o4 = reinterpret_cast<float4*>(out);

    uint2 p[NORM_UNITS];
#pragma unroll
    for (int k = 0; k < NORM_UNITS; k++)
        p[k] = __ldlu(src + unit0 + NORM_TPB * k);   // front-batched, coalesced

#pragma unroll
    for (int k = 0; k < NORM_UNITS; k++) {
        __half2 h0 = *reinterpret_cast<__half2*>(&p[k].x);
        __half2 h1 = *reinterpret_cast<__half2*>(&p[k].y);
        float2 a = __half22float2(h0);
        float2 b = __half22float2(h1);
        float4 v;
        v.x = fmaf(a.x, inv, neg);
        v.y = fmaf(a.y, inv, neg);
        v.z = fmaf(b.x, inv, neg);
        v.w = fmaf(b.y, inv, neg);
        __stcs(o4 + unit0 + NORM_TPB * k, v);
    }
}

extern "C" void kernel_launch(void* const* d_in, const int* in_sizes, int n_in,
                              void* d_out, int out_size)
{
    const float* rewards = (const float*)d_in[0];
    const float* dones   = (const float*)d_in[1];
    float* out = (float*)d_out;

    scan_kernel<<<B_ROWS, SCAN_THREADS>>>(rewards, dones);
    norm_kernel<<<B_ROWS, NORM_TPB>>>(out);
}

// round 13
// speedup vs baseline: 1.0800x; 1.0496x over previous
#include <cuda_runtime.h>
#include <cuda_fp16.h>
#include <math.h>

#define B_ROWS 4096
#define T_LEN  8192
#define SCAN_THREADS 512
#define NWARPS (SCAN_THREADS / 32)     // 16
#define CHUNK (T_LEN / SCAN_THREADS)   // 16
#define GROUPS (T_LEN / 4)             // 2048 float4-groups per row
#define GAMMA 0.99f
#define GAMMA16 0.8514577710948755f    // 0.99^16
#define EPS_N 1e-9f
#define RPAD 513                       // padded row stride (words) for transpose smem

// Scratch (device globals; no allocations allowed).
__device__ float    g_row_sum[B_ROWS];
__device__ float    g_row_inv[B_ROWS];
__device__ float    g_mean_val;
__device__ unsigned g_count;           // zero-init; atomicInc wraps -> self-reset per launch
// fp16 staging for unnormalized returns: 64 MB, L2-resident in steady state.
__device__ __align__(128) __half g_ret_h[(size_t)B_ROWS * T_LEN];

// ───────────────────────── scan: one block per row ─────────────────────────
// x_t = r_t + a_t * x_{t+1},  a_t = GAMMA*(1-done_t),  done in {0,1} exactly.
// Register diet: values live in smem (transposed), not in a r[16] array, so the
// kernel fits 32 regs -> 4 CTAs/SM (64 warps) for more in-flight DRAM traffic.
__global__ __launch_bounds__(SCAN_THREADS, 4)
void scan_kernel(const float* __restrict__ rewards,
                 const float* __restrict__ dones)
{
    const int row  = blockIdx.x;
    const int tid  = threadIdx.x;
    const int lane = tid & 31;
    const int wid  = tid >> 5;
    const size_t row_off = (size_t)row * T_LEN;

    __shared__ float s_rew[16 * RPAD];          // transposed values (in-place updated)
    __shared__ __align__(16) unsigned s_db[GROUPS];  // 4 done-bytes packed per word
    __shared__ float sWA[NWARPS], sWB[NWARPS], sCB[NWARPS];
    __shared__ float sS[NWARPS],  sQ[NWARPS];
    __shared__ unsigned s_last;

    // ── Phase 1: coalesced load (lane-contiguous float4 groups) -> smem ──
    const float4* r4 = reinterpret_cast<const float4*>(rewards + row_off);
    const float4* d4 = reinterpret_cast<const float4*>(dones   + row_off);
#pragma unroll
    for (int k = 0; k < 4; k++) {
        const int g = tid + 512 * k;
        float4 rv = __ldcs(r4 + g);
        float4 dv = __ldcs(d4 + g);
        const int c = (g & 3) * 4;
        const int q = g >> 2;
        s_rew[(c + 0) * RPAD + q] = rv.x;
        s_rew[(c + 1) * RPAD + q] = rv.y;
        s_rew[(c + 2) * RPAD + q] = rv.z;
        s_rew[(c + 3) * RPAD + q] = rv.w;
        unsigned p = (dv.x != 0.0f ? 1u : 0u)
                   | (dv.y != 0.0f ? 1u : 0u) << 8
                   | (dv.z != 0.0f ? 1u : 0u) << 16
                   | (dv.w != 0.0f ? 1u : 0u) << 24;
        s_db[g] = p;
    }
    __syncthreads();

    // ── Phase 2: compose chunk affine map, reading values from smem ──
    unsigned mask = 0;
    {
        const uint4 dw = *reinterpret_cast<const uint4*>(&s_db[tid * 4]);
        const unsigned w[4] = {dw.x, dw.y, dw.z, dw.w};
#pragma unroll
        for (int q = 0; q < 4; q++) {
            mask |= ((w[q] >> 0)  & 1u) << (4*q + 0);
            mask |= ((w[q] >> 8)  & 1u) << (4*q + 1);
            mask |= ((w[q] >> 16) & 1u) << (4*q + 2);
            mask |= ((w[q] >> 24) & 1u) << (4*q + 3);
        }
    }

    float A  = (mask == 0u) ? GAMMA16 : 0.0f;
    float Bc = 0.0f;
#pragma unroll
    for (int t = CHUNK - 1; t >= 0; t--) {
        float v = s_rew[t * RPAD + tid];        // conflict-free (lane-contiguous)
        float f = fmaf(GAMMA, Bc, v);
        Bc = (mask & (1u << t)) ? v : f;
    }

    // Warp-level inclusive SUFFIX scan via shuffles.
#pragma unroll
    for (int d = 1; d < 32; d <<= 1) {
        float A2 = __shfl_down_sync(0xFFFFFFFFu, A, d);
        float B2 = __shfl_down_sync(0xFFFFFFFFu, Bc, d);
        if (lane + d < 32) {
            Bc = fmaf(A, B2, Bc);
            A  = A * A2;
        }
    }

    if (lane == 0) { sWA[wid] = A; sWB[wid] = Bc; }
    __syncthreads();

    if (wid == 0) {
        float wA = (lane < NWARPS) ? sWA[lane] : 1.0f;
        float wB = (lane < NWARPS) ? sWB[lane] : 0.0f;
#pragma unroll
        for (int d = 1; d < NWARPS; d <<= 1) {
            float A2 = __shfl_down_sync(0xFFFFFFFFu, wA, d);
            float B2 = __shfl_down_sync(0xFFFFFFFFu, wB, d);
            if (lane + d < NWARPS) {
                wB = fmaf(wA, B2, wB);
                wA = wA * A2;
            }
        }
        float eB = __shfl_down_sync(0xFFFFFFFFu, wB, 1);
        if (lane == NWARPS - 1) eB = 0.0f;
        if (lane < NWARPS) sCB[lane] = eB;
    }
    __syncthreads();

    float cB   = sCB[wid];
    float totB = fmaf(A, cB, Bc);
    float carry = __shfl_down_sync(0xFFFFFFFFu, totB, 1);
    if (lane == 31) carry = cB;        // tid==511 -> cB==0, correct

    // ── Phase 3: replay from smem, write carries back IN PLACE (same-thread
    // RAW within smem: no barrier needed), accumulate moments ──
    float sum = 0.0f, sq = 0.0f;
#pragma unroll
    for (int t = CHUNK - 1; t >= 0; t--) {
        float v = s_rew[t * RPAD + tid];
        float f = fmaf(GAMMA, carry, v);
        carry = (mask & (1u << t)) ? v : f;
        s_rew[t * RPAD + tid] = carry;
        sum += carry;
        sq = fmaf(carry, carry, sq);
    }

    // ── Phase 4: re-read own values, pack fp16, thread-contiguous store ──
    {
        __half2 h[CHUNK / 2];
#pragma unroll
        for (int i = 0; i < CHUNK / 2; i++)
            h[i] = __floats2half2_rn(s_rew[(2*i) * RPAD + tid],
                                     s_rew[(2*i+1) * RPAD + tid]);
        uint4* dst = reinterpret_cast<uint4*>(g_ret_h + row_off + tid * CHUNK);
        const uint4* srcv = reinterpret_cast<const uint4*>(h);
        dst[0] = srcv[0];
        dst[1] = srcv[1];
    }

    // Block reduction of (sum, sq).
#pragma unroll
    for (int d = 16; d > 0; d >>= 1) {
        sum += __shfl_down_sync(0xFFFFFFFFu, sum, d);
        sq  += __shfl_down_sync(0xFFFFFFFFu, sq,  d);
    }
    if (lane == 0) { sS[wid] = sum; sQ[wid] = sq; }
    __syncthreads();
    if (tid < 32) {
        float ts = (lane < NWARPS) ? sS[lane] : 0.0f;
        float tq = (lane < NWARPS) ? sQ[lane] : 0.0f;
#pragma unroll
        for (int d = NWARPS / 2; d > 0; d >>= 1) {
            ts += __shfl_down_sync(0xFFFFFFFFu, ts, d);
            tq += __shfl_down_sync(0xFFFFFFFFu, tq, d);
        }
        if (lane == 0) {
            float mean = ts / (float)T_LEN;
            float var  = (tq - ts * mean) / (float)(T_LEN - 1);   // ddof=1
            g_row_sum[row] = ts;
            g_row_inv[row] = 1.0f / (sqrtf(fmaxf(var, 0.0f)) + EPS_N);
        }
    }

    // Last block to finish reduces the 4096 row sums -> global mean.
    if (tid == 0) {
        __threadfence();
        unsigned prev = atomicInc(&g_count, B_ROWS - 1);   // wraps to 0: self-reset
        s_last = (prev == B_ROWS - 1) ? 1u : 0u;
    }
    __syncthreads();
    if (s_last) {
        float s = 0.0f;
#pragma unroll
        for (int i = 0; i < B_ROWS / SCAN_THREADS; i++)
            s += __ldcg(&g_row_sum[tid + i * SCAN_THREADS]);
#pragma unroll
        for (int d = 16; d > 0; d >>= 1)
            s += __shfl_down_sync(0xFFFFFFFFu, s, d);
        if (lane == 0) sS[wid] = s;
        __syncthreads();
        if (tid < 32) {
            float t = (lane < NWARPS) ? sS[lane] : 0.0f;
#pragma unroll
            for (int d = 16; d > 0; d >>= 1)
                t += __shfl_down_sync(0xFFFFFFFFu, t, d);
            if (tid == 0)
                g_mean_val = t / ((float)B_ROWS * (float)T_LEN);
        }
    }
}

// ── normalize: R10-proven config (best measured: 28.4 µs). One block per row;
// 512 threads, 4 unit-interleaved loads (unit = 4 elements). ──
__global__ __launch_bounds__(512)
void norm_kernel(float* __restrict__ out)
{
    const int row = blockIdx.x;
    const float inv = g_row_inv[row];
    const float neg = -g_mean_val * inv;
    const size_t unit0 = (size_t)row * GROUPS + threadIdx.x;

    const uint2* src = reinterpret_cast<const uint2*>(g_ret_h);
    float4* o4 = reinterpret_cast<float4*>(out);

    uint2 p[4];
#pragma unroll
    for (int k = 0; k < 4; k++)
        p[k] = __ldlu(src + unit0 + 512 * k);     // front-batched, coalesced

#pragma unroll
    for (int k = 0; k < 4; k++) {
        __half2 h0 = *reinterpret_cast<__half2*>(&p[k].x);
        __half2 h1 = *reinterpret_cast<__half2*>(&p[k].y);
        float2 a = __half22float2(h0);
        float2 b = __half22float2(h1);
        float4 v;
        v.x = fmaf(a.x, inv, neg);
        v.y = fmaf(a.y, inv, neg);
        v.z = fmaf(b.x, inv, neg);
        v.w = fmaf(b.y, inv, neg);
        __stcs(o4 + unit0 + 512 * k, v);
    }
}

extern "C" void kernel_launch(void* const* d_in, const int* in_sizes, int n_in,
                              void* d_out, int out_size)
{
    const float* rewards = (const float*)d_in[0];
    const float* dones   = (const float*)d_in[1];
    float* out = (float*)d_out;

    scan_kernel<<<B_ROWS, SCAN_THREADS>>>(rewards, dones);
    norm_kernel<<<B_ROWS, 512>>>(out);
}